// round 6
// baseline (speedup 1.0000x reference)
#include <cuda_runtime.h>

// ---------------------------------------------------------------------------
// Sparse masked 3D U-Net (presetUResNet) on 96^3 grid, fp32.
// R5: warp-uniform cout mapping. A warp handles 32 consecutive occupied voxels
// and ONE 8-cout tile, so all weight loads are warp-broadcast LDG.128 (1 line)
// and input gathers are float4 over the [c/4][v][4] layout. No smem, no syncs.
// ---------------------------------------------------------------------------

constexpr int D0 = 96, D1 = 48, D2 = 24;
constexpr int V0 = D0 * D0 * D0;
constexpr int V1 = D1 * D1 * D1;
constexpr int V2 = D2 * D2 * D2;

// ---- scratch arena (floats) ----
constexpr int OFF_XM    = 0;
constexpr int OFF_SKIP0 = OFF_XM    + V0;
constexpr int OFF_UP1   = OFF_SKIP0 + 16 * V0;
constexpr int OFF_T32   = OFF_UP1   + 16 * V0;
constexpr int OFF_HA    = OFF_T32   + 32 * V0;
constexpr int OFF_HB    = OFF_HA    + 32 * V1;
constexpr int OFF_S1    = OFF_HB    + 32 * V1;
constexpr int OFF_H64   = OFF_S1    + 32 * V1;
constexpr int OFF_CA    = OFF_H64   + 64 * V1;
constexpr int OFF_CB    = OFF_CA    + 64 * V2;
constexpr int FEAT_END  = OFF_CB    + 64 * V2;
constexpr int OFF_M1    = FEAT_END;
constexpr int OFF_M2    = OFF_M1 + V1;
constexpr int OFF_W     = OFF_M2 + V2;
// transposed weights: [(t*Cin + ci)*Copad + o]
constexpr int WO_IN  = OFF_W;
constexpr int WO_E0D = WO_IN  + 1  * 27 * 16;
constexpr int WO_E0A = WO_E0D + 16 * 8  * 32;
constexpr int WO_E0B = WO_E0A + 32 * 27 * 32;
constexpr int WO_E1D = WO_E0B + 32 * 27 * 32;
constexpr int WO_E1A = WO_E1D + 32 * 8  * 64;
constexpr int WO_E1B = WO_E1A + 64 * 27 * 64;
constexpr int WO_D0U = WO_E1B + 64 * 27 * 64;
constexpr int WO_D0A = WO_D0U + 64 * 8  * 32;
constexpr int WO_D0B = WO_D0A + 64 * 27 * 64;
constexpr int WO_D1U = WO_D0B + 64 * 27 * 32;
constexpr int WO_D1A = WO_D1U + 32 * 8  * 16;
constexpr int WO_D1B = WO_D1A + 32 * 27 * 32;
constexpr int WO_OA  = WO_D1B + 32 * 27 * 16;
constexpr int WO_OB  = WO_OA  + 16 * 27 * 16;
constexpr int SCRATCH_TOTAL = WO_OB + 16 * 27 * 8;

__device__ __align__(256) float g_scratch[SCRATCH_TOTAL];  // zero-initialized
__device__ int g_list0[V0];
__device__ int g_list1[V1];
__device__ int g_list2[V2];
__device__ int g_cnt[4];

// ---------------------------------------------------------------------------
// prep kernels
// ---------------------------------------------------------------------------

__global__ void prep1_kernel(const float* __restrict__ x,
                             const float* __restrict__ occ,
                             float* __restrict__ out, int outn) {
    int stride = gridDim.x * blockDim.x;
    int gt = blockIdx.x * blockDim.x + threadIdx.x;
    float4 z4 = make_float4(0.f, 0.f, 0.f, 0.f);
    float4* o4 = reinterpret_cast<float4*>(out);
    for (int i = gt; i < outn / 4; i += stride) o4[i] = z4;
    for (int i = gt; i < V0; i += stride) g_scratch[OFF_XM + i] = x[i] * occ[i];
    for (int i = gt; i < V1; i += stride) {
        int xx = i % D1, yy = (i / D1) % D1, zz = i / (D1 * D1);
        float m = 0.f;
        #pragma unroll
        for (int dz = 0; dz < 2; dz++)
            #pragma unroll
            for (int dy = 0; dy < 2; dy++)
                #pragma unroll
                for (int dx = 0; dx < 2; dx++)
                    m = fmaxf(m, occ[((2 * zz + dz) * D0 + 2 * yy + dy) * D0 + 2 * xx + dx]);
        g_scratch[OFF_M1 + i] = m;
    }
    for (int i = gt; i < V2; i += stride) {
        int xx = i % D2, yy = (i / D2) % D2, zz = i / (D2 * D2);
        float m = 0.f;
        for (int dz = 0; dz < 4; dz++)
            for (int dy = 0; dy < 4; dy++)
                #pragma unroll
                for (int dx = 0; dx < 4; dx++)
                    m = fmaxf(m, occ[((4 * zz + dz) * D0 + 4 * yy + dy) * D0 + 4 * xx + dx]);
        g_scratch[OFF_M2 + i] = m;
    }
    if (gt == 0) { g_cnt[0] = 0; g_cnt[1] = 0; g_cnt[2] = 0; g_cnt[3] = 0; }
}

__global__ void lists_kernel(const float* __restrict__ occ) {
    const float* mask; int n; int* list; int* cnt;
    if (blockIdx.y == 0)      { mask = occ;                n = V0; list = g_list0; cnt = &g_cnt[0]; }
    else if (blockIdx.y == 1) { mask = g_scratch + OFF_M1; n = V1; list = g_list1; cnt = &g_cnt[1]; }
    else                      { mask = g_scratch + OFF_M2; n = V2; list = g_list2; cnt = &g_cnt[2]; }
    int lane = threadIdx.x & 31;
    for (int i = blockIdx.x * blockDim.x + threadIdx.x; i < n + 31;
         i += gridDim.x * blockDim.x) {
        bool pred = (i < n) && (mask[i] > 0.5f);
        unsigned bal = __ballot_sync(0xffffffffu, pred);
        int leader = __ffs(bal) - 1;
        int base = 0;
        if (bal && lane == leader) base = atomicAdd(cnt, __popc(bal));
        base = __shfl_sync(0xffffffffu, base, leader < 0 ? 0 : leader);
        if (pred) list[base + __popc(bal & ((1u << lane) - 1))] = i;
    }
}

struct WPtrs { const float* p[15]; };
__device__ const int TW_DIMS[15][4] = {
    {16, 1, 27, 16}, {32, 16, 8, 32}, {32, 32, 27, 32}, {32, 32, 27, 32},
    {64, 32, 8, 64}, {64, 64, 27, 64}, {64, 64, 27, 64}, {32, 64, 8, 32},
    {64, 64, 27, 64}, {32, 64, 27, 32}, {16, 32, 8, 16}, {32, 32, 27, 32},
    {16, 32, 27, 16}, {16, 16, 27, 16}, {5, 16, 27, 8}};
__device__ const int TW_OFF[15] = {
    WO_IN, WO_E0D, WO_E0A, WO_E0B, WO_E1D, WO_E1A, WO_E1B, WO_D0U,
    WO_D0A, WO_D0B, WO_D1U, WO_D1A, WO_D1B, WO_OA, WO_OB};

__global__ void tw_kernel(WPtrs wp) {
    int e = blockIdx.y;
    int Cout = TW_DIMS[e][0], Cin = TW_DIMS[e][1], K3 = TW_DIMS[e][2], Copad = TW_DIMS[e][3];
    const float* w = wp.p[e];
    float* wt = g_scratch + TW_OFF[e];
    int total = Cin * K3 * Copad;
    for (int i = blockIdx.x * blockDim.x + threadIdx.x; i < total;
         i += gridDim.x * blockDim.x) {
        int o = i % Copad;
        int r = i / Copad;
        int t = r / Cin, ci = r % Cin;
        wt[i] = (o < Cout) ? w[(o * Cin + ci) * K3 + t] : 0.f;
    }
}

// ---------------------------------------------------------------------------
// conv3: warp = 32 consecutive list voxels x one co8 tile (broadcast weights)
// ---------------------------------------------------------------------------

__device__ __forceinline__ void fma8(float* acc, float f, const float4 w0, const float4 w1) {
    acc[0] += f * w0.x; acc[1] += f * w0.y; acc[2] += f * w0.z; acc[3] += f * w0.w;
    acc[4] += f * w1.x; acc[5] += f * w1.y; acc[6] += f * w1.z; acc[7] += f * w1.w;
}

template <int ICGA, int ICGB, int OCG8, bool RELU>
__global__ __launch_bounds__(256)
void conv3_bc(const float* __restrict__ inA, const float* __restrict__ inB,
              const float* __restrict__ wt, float* __restrict__ out,
              const int* __restrict__ list, const int* __restrict__ cnt,
              int cntIdx, int D) {
    constexpr int ICGT = ICGA + ICGB;
    constexpr int CIN = ICGT * 4;
    constexpr int COPAD = OCG8 * 8;
    const int vol = D * D * D;
    const int n = cnt[cntIdx];
    const int nvch = (n + 31) >> 5;
    const long nitems = (long)nvch * OCG8;
    const int wpb = blockDim.x >> 5;
    const int warpsTotal = gridDim.x * wpb;
    const int gw = blockIdx.x * wpb + (threadIdx.x >> 5);
    const int lane = threadIdx.x & 31;

    for (long item = gw; item < nitems; item += warpsTotal) {
        int vch = (int)(item / OCG8);
        int co8 = (int)(item % OCG8) * 8;
        int idx = vch * 32 + lane;
        bool active = idx < n;
        int v = list[active ? idx : n - 1];
        int x0 = v % D, y0 = (v / D) % D, z0 = v / (D * D);
        bool xm0 = x0 >= 1, xm2 = x0 < D - 1;
        bool ym0 = y0 >= 1, ym2 = y0 < D - 1;
        float acc[8];
        #pragma unroll
        for (int k = 0; k < 8; k++) acc[k] = 0.f;

        #pragma unroll 1
        for (int g = 0; g < ICGT; g++) {
            const float* base = (g < ICGA) ? inA + (long)g * vol * 4
                                           : inB + (long)(g - ICGA) * vol * 4;
            #pragma unroll
            for (int p = 0; p < 3; p++) {
                int zz = z0 + p - 1;
                bool zok = (unsigned)zz < (unsigned)D;
                #pragma unroll
                for (int r = 0; r < 3; r++) {
                    int dy = r - 1;
                    bool yok = zok && (dy < 0 ? ym0 : (dy > 0 ? ym2 : true));
                    int rb = (zz * D + (y0 + dy)) * D + x0;
                    float4 iv[3];
                    #pragma unroll
                    for (int q = 0; q < 3; q++) {
                        int dx = q - 1;
                        bool ok = yok && (dx < 0 ? xm0 : (dx > 0 ? xm2 : true));
                        iv[q] = ok ? __ldg(reinterpret_cast<const float4*>(
                                         base + (long)(rb + dx) * 4))
                                   : make_float4(0.f, 0.f, 0.f, 0.f);
                    }
                    #pragma unroll
                    for (int q = 0; q < 3; q++) {
                        int t = (p * 3 + r) * 3 + q;
                        const float* wrow = wt + ((long)t * CIN + 4 * g) * COPAD + co8;
                        float f[4] = {iv[q].x, iv[q].y, iv[q].z, iv[q].w};
                        #pragma unroll
                        for (int j = 0; j < 4; j++) {
                            float4 w0 = __ldg(reinterpret_cast<const float4*>(wrow + j * COPAD));
                            float4 w1 = __ldg(reinterpret_cast<const float4*>(wrow + j * COPAD + 4));
                            fma8(acc, f[j], w0, w1);
                        }
                    }
                }
            }
        }
        if (RELU) {
            #pragma unroll
            for (int k = 0; k < 8; k++) acc[k] = fmaxf(acc[k], 0.f);
        }
        if (active) {
            int ocg = co8 >> 2;
            *reinterpret_cast<float4*>(out + ((long)ocg * vol + v) * 4) =
                make_float4(acc[0], acc[1], acc[2], acc[3]);
            *reinterpret_cast<float4*>(out + ((long)(ocg + 1) * vol + v) * 4) =
                make_float4(acc[4], acc[5], acc[6], acc[7]);
        }
    }
}

// ---------------------------------------------------------------------------
// down2 / up2 with the same warp-uniform cout mapping
// ---------------------------------------------------------------------------

template <int ICG, int OCG8>
__global__ __launch_bounds__(256)
void down2_bc(const float* __restrict__ in, const float* __restrict__ wt,
              float* __restrict__ out, const int* __restrict__ list,
              const int* __restrict__ cnt, int cntIdx, int Dc) {
    constexpr int CIN = ICG * 4;
    constexpr int COPAD = OCG8 * 8;
    const int Df = Dc * 2;
    const int volf = Df * Df * Df;
    const int volc = Dc * Dc * Dc;
    const int n = cnt[cntIdx];
    const int nvch = (n + 31) >> 5;
    const long nitems = (long)nvch * OCG8;
    const int wpb = blockDim.x >> 5;
    const int warpsTotal = gridDim.x * wpb;
    const int gw = blockIdx.x * wpb + (threadIdx.x >> 5);
    const int lane = threadIdx.x & 31;

    for (long item = gw; item < nitems; item += warpsTotal) {
        int vch = (int)(item / OCG8);
        int co8 = (int)(item % OCG8) * 8;
        int idx = vch * 32 + lane;
        bool active = idx < n;
        int v = list[active ? idx : n - 1];
        int x0 = v % Dc, y0 = (v / Dc) % Dc, z0 = v / (Dc * Dc);
        float acc[8];
        #pragma unroll
        for (int k = 0; k < 8; k++) acc[k] = 0.f;
        #pragma unroll 1
        for (int g = 0; g < ICG; g++) {
            const float* base = in + (long)g * volf * 4;
            #pragma unroll
            for (int t = 0; t < 8; t++) {
                int tz = t >> 2, ty = (t >> 1) & 1, tx = t & 1;
                int noff = ((2 * z0 + tz) * Df + 2 * y0 + ty) * Df + 2 * x0 + tx;
                float4 iv = __ldg(reinterpret_cast<const float4*>(base + (long)noff * 4));
                const float* wrow = wt + ((long)t * CIN + 4 * g) * COPAD + co8;
                float f[4] = {iv.x, iv.y, iv.z, iv.w};
                #pragma unroll
                for (int j = 0; j < 4; j++) {
                    float4 w0 = __ldg(reinterpret_cast<const float4*>(wrow + j * COPAD));
                    float4 w1 = __ldg(reinterpret_cast<const float4*>(wrow + j * COPAD + 4));
                    fma8(acc, f[j], w0, w1);
                }
            }
        }
        if (active) {
            int ocg = co8 >> 2;
            *reinterpret_cast<float4*>(out + ((long)ocg * volc + v) * 4) =
                make_float4(acc[0], acc[1], acc[2], acc[3]);
            *reinterpret_cast<float4*>(out + ((long)(ocg + 1) * volc + v) * 4) =
                make_float4(acc[4], acc[5], acc[6], acc[7]);
        }
    }
}

template <int ICG, int OCG8>
__global__ __launch_bounds__(256)
void up2_bc(const float* __restrict__ in, const float* __restrict__ wt,
            float* __restrict__ out, const int* __restrict__ list,
            const int* __restrict__ cnt, int cntIdx, int Df) {
    constexpr int CIN = ICG * 4;
    constexpr int COPAD = OCG8 * 8;
    const int Dc = Df / 2;
    const int volf = Df * Df * Df;
    const int volc = Dc * Dc * Dc;
    const int n = cnt[cntIdx];
    const int nvch = (n + 31) >> 5;
    const long nitems = (long)nvch * OCG8;
    const int wpb = blockDim.x >> 5;
    const int warpsTotal = gridDim.x * wpb;
    const int gw = blockIdx.x * wpb + (threadIdx.x >> 5);
    const int lane = threadIdx.x & 31;

    for (long item = gw; item < nitems; item += warpsTotal) {
        int vch = (int)(item / OCG8);
        int co8 = (int)(item % OCG8) * 8;
        int idx = vch * 32 + lane;
        bool active = idx < n;
        int v = list[active ? idx : n - 1];
        int x0 = v % Df, y0 = (v / Df) % Df, z0 = v / (Df * Df);
        int t = ((1 - (z0 & 1)) * 2 + (1 - (y0 & 1))) * 2 + (1 - (x0 & 1));
        int coff = ((z0 >> 1) * Dc + (y0 >> 1)) * Dc + (x0 >> 1);
        float acc[8];
        #pragma unroll
        for (int k = 0; k < 8; k++) acc[k] = 0.f;
        #pragma unroll 1
        for (int g = 0; g < ICG; g++) {
            float4 iv = __ldg(reinterpret_cast<const float4*>(
                in + ((long)g * volc + coff) * 4));
            const float* wrow = wt + ((long)t * CIN + 4 * g) * COPAD + co8;
            float f[4] = {iv.x, iv.y, iv.z, iv.w};
            #pragma unroll
            for (int j = 0; j < 4; j++) {
                float4 w0 = __ldg(reinterpret_cast<const float4*>(wrow + j * COPAD));
                float4 w1 = __ldg(reinterpret_cast<const float4*>(wrow + j * COPAD + 4));
                fma8(acc, f[j], w0, w1);
            }
        }
        if (active) {
            int ocg = co8 >> 2;
            *reinterpret_cast<float4*>(out + ((long)ocg * volf + v) * 4) =
                make_float4(acc[0], acc[1], acc[2], acc[3]);
            *reinterpret_cast<float4*>(out + ((long)(ocg + 1) * volf + v) * 4) =
                make_float4(acc[4], acc[5], acc[6], acc[7]);
        }
    }
}

// ---------------------------------------------------------------------------
// input conv (1->16) and output conv (16->5)
// ---------------------------------------------------------------------------

__global__ __launch_bounds__(256)
void conv_in_bc(const float* __restrict__ xm, const float* __restrict__ wt,
                float* __restrict__ out, const int* __restrict__ list,
                const int* __restrict__ cnt) {
    const int D = D0, vol = V0;
    int n = cnt[0];
    for (int w = blockIdx.x * blockDim.x + threadIdx.x; w < n;
         w += gridDim.x * blockDim.x) {
        int v = list[w];
        int x0 = v % D, y0 = (v / D) % D, z0 = v / (D * D);
        bool xm0 = x0 >= 1, xm2 = x0 < D - 1;
        bool ym0 = y0 >= 1, ym2 = y0 < D - 1;
        float acc[16];
        #pragma unroll
        for (int k = 0; k < 16; k++) acc[k] = 0.f;
        #pragma unroll
        for (int p = 0; p < 3; p++) {
            int zz = z0 + p - 1;
            bool zok = (unsigned)zz < (unsigned)D;
            #pragma unroll
            for (int r = 0; r < 3; r++) {
                int dy = r - 1;
                bool yok = zok && (dy < 0 ? ym0 : (dy > 0 ? ym2 : true));
                int rb = (zz * D + (y0 + dy)) * D + x0;
                float iv[3];
                #pragma unroll
                for (int q = 0; q < 3; q++) {
                    int dx = q - 1;
                    bool ok = yok && (dx < 0 ? xm0 : (dx > 0 ? xm2 : true));
                    iv[q] = ok ? __ldg(xm + rb + dx) : 0.f;
                }
                #pragma unroll
                for (int q = 0; q < 3; q++) {
                    const float* wp = wt + ((p * 3 + r) * 3 + q) * 16;
                    #pragma unroll
                    for (int c = 0; c < 16; c += 4) {
                        float4 wv = __ldg(reinterpret_cast<const float4*>(wp + c));
                        acc[c + 0] += iv[q] * wv.x; acc[c + 1] += iv[q] * wv.y;
                        acc[c + 2] += iv[q] * wv.z; acc[c + 3] += iv[q] * wv.w;
                    }
                }
            }
        }
        #pragma unroll
        for (int k = 0; k < 16; k += 4)
            *reinterpret_cast<float4*>(out + ((long)(k / 4) * vol + v) * 4) =
                make_float4(acc[k], acc[k + 1], acc[k + 2], acc[k + 3]);
    }
}

__global__ __launch_bounds__(256)
void conv_out_bc(const float* __restrict__ in, const float* __restrict__ wt,
                 float* __restrict__ out, const int* __restrict__ list,
                 const int* __restrict__ cnt) {
    const int D = D0, vol = V0;
    const int n = cnt[0];
    const int nvch = (n + 31) >> 5;
    const int wpb = blockDim.x >> 5;
    const int warpsTotal = gridDim.x * wpb;
    const int gw = blockIdx.x * wpb + (threadIdx.x >> 5);
    const int lane = threadIdx.x & 31;

    for (int item = gw; item < nvch; item += warpsTotal) {
        int idx = item * 32 + lane;
        bool active = idx < n;
        int v = list[active ? idx : n - 1];
        int x0 = v % D, y0 = (v / D) % D, z0 = v / (D * D);
        bool xm0 = x0 >= 1, xm2 = x0 < D - 1;
        bool ym0 = y0 >= 1, ym2 = y0 < D - 1;
        float acc[8];
        #pragma unroll
        for (int k = 0; k < 8; k++) acc[k] = 0.f;
        #pragma unroll 1
        for (int g = 0; g < 4; g++) {
            const float* base = in + (long)g * vol * 4;
            #pragma unroll
            for (int p = 0; p < 3; p++) {
                int zz = z0 + p - 1;
                bool zok = (unsigned)zz < (unsigned)D;
                #pragma unroll
                for (int r = 0; r < 3; r++) {
                    int dy = r - 1;
                    bool yok = zok && (dy < 0 ? ym0 : (dy > 0 ? ym2 : true));
                    int rb = (zz * D + (y0 + dy)) * D + x0;
                    float4 iv[3];
                    #pragma unroll
                    for (int q = 0; q < 3; q++) {
                        int dx = q - 1;
                        bool ok = yok && (dx < 0 ? xm0 : (dx > 0 ? xm2 : true));
                        iv[q] = ok ? __ldg(reinterpret_cast<const float4*>(
                                         base + (long)(rb + dx) * 4))
                                   : make_float4(0.f, 0.f, 0.f, 0.f);
                    }
                    #pragma unroll
                    for (int q = 0; q < 3; q++) {
                        int t = (p * 3 + r) * 3 + q;
                        const float* wrow = wt + ((long)t * 16 + 4 * g) * 8;
                        float f[4] = {iv[q].x, iv[q].y, iv[q].z, iv[q].w};
                        #pragma unroll
                        for (int j = 0; j < 4; j++) {
                            float4 w0 = __ldg(reinterpret_cast<const float4*>(wrow + j * 8));
                            float4 w1 = __ldg(reinterpret_cast<const float4*>(wrow + j * 8 + 4));
                            fma8(acc, f[j], w0, w1);
                        }
                    }
                }
            }
        }
        if (active) {
            #pragma unroll
            for (int c = 0; c < 5; c++) out[(long)c * vol + v] = acc[c];
        }
    }
}

// ---------------------------------------------------------------------------
// launch
// ---------------------------------------------------------------------------

static inline int nblk_w(long items_max) {   // warp-item kernels, 8 warps/block
    long b = (items_max + 7) / 8;
    return (int)(b < 2048 ? (b > 1 ? b : 1) : 2048);
}

extern "C" void kernel_launch(void* const* d_in, const int* in_sizes, int n_in,
                              void* d_out, int out_size) {
    (void)in_sizes; (void)n_in;
    const float* x   = (const float*)d_in[0];
    const float* occ = (const float*)d_in[1];
    float* out = (float*)d_out;

    float* SB = nullptr;
    int *L0 = nullptr, *L1 = nullptr, *L2 = nullptr, *CNT = nullptr;
    cudaGetSymbolAddress((void**)&SB,  g_scratch);
    cudaGetSymbolAddress((void**)&L0,  g_list0);
    cudaGetSymbolAddress((void**)&L1,  g_list1);
    cudaGetSymbolAddress((void**)&L2,  g_list2);
    cudaGetSymbolAddress((void**)&CNT, g_cnt);

    prep1_kernel<<<1024, 256>>>(x, occ, out, out_size);
    lists_kernel<<<dim3(432, 3), 256>>>(occ);
    WPtrs wp;
    for (int i = 0; i < 15; i++) wp.p[i] = (const float*)d_in[2 + i];
    tw_kernel<<<dim3(216, 15), 256>>>(wp);

    // worst-case voxel chunks per level (actual trip count uses device cnt)
    const long VC0 = (V0 + 31) / 32, VC1 = (V1 + 31) / 32, VC2 = (V2 + 31) / 32;

    // input conv 1->16 @96
    conv_in_bc<<<1024, 256>>>(SB + OFF_XM, SB + WO_IN, SB + OFF_SKIP0, L0, CNT);

    // encoder level 0
    down2_bc<4, 4><<<nblk_w(VC1 * 4), 256>>>(
        SB + OFF_SKIP0, SB + WO_E0D, SB + OFF_HA, L1, CNT, 1, D1);
    conv3_bc<8, 0, 4, true><<<nblk_w(VC1 * 4), 256>>>(
        SB + OFF_HA, nullptr, SB + WO_E0A, SB + OFF_HB, L1, CNT, 1, D1);
    conv3_bc<8, 0, 4, false><<<nblk_w(VC1 * 4), 256>>>(
        SB + OFF_HB, nullptr, SB + WO_E0B, SB + OFF_S1, L1, CNT, 1, D1);

    // encoder level 1
    down2_bc<8, 8><<<nblk_w(VC2 * 8), 256>>>(
        SB + OFF_S1, SB + WO_E1D, SB + OFF_CA, L2, CNT, 2, D2);
    conv3_bc<16, 0, 8, true><<<nblk_w(VC2 * 8), 256>>>(
        SB + OFF_CA, nullptr, SB + WO_E1A, SB + OFF_CB, L2, CNT, 2, D2);
    conv3_bc<16, 0, 8, false><<<nblk_w(VC2 * 8), 256>>>(
        SB + OFF_CB, nullptr, SB + WO_E1B, SB + OFF_CA, L2, CNT, 2, D2);

    // decoder stage 0 (to level 1)
    up2_bc<16, 4><<<nblk_w(VC1 * 4), 256>>>(
        SB + OFF_CA, SB + WO_D0U, SB + OFF_HA, L1, CNT, 1, D1);
    conv3_bc<8, 8, 8, true><<<nblk_w(VC1 * 8), 256>>>(
        SB + OFF_HA, SB + OFF_S1, SB + WO_D0A, SB + OFF_H64, L1, CNT, 1, D1);
    conv3_bc<16, 0, 4, false><<<nblk_w(VC1 * 4), 256>>>(
        SB + OFF_H64, nullptr, SB + WO_D0B, SB + OFF_HB, L1, CNT, 1, D1);

    // decoder stage 1 (to level 0)
    up2_bc<8, 2><<<nblk_w(VC0 * 2), 256>>>(
        SB + OFF_HB, SB + WO_D1U, SB + OFF_UP1, L0, CNT, 0, D0);
    conv3_bc<4, 4, 4, true><<<nblk_w(VC0 * 4), 256>>>(
        SB + OFF_UP1, SB + OFF_SKIP0, SB + WO_D1A, SB + OFF_T32, L0, CNT, 0, D0);
    conv3_bc<8, 0, 2, false><<<nblk_w(VC0 * 2), 256>>>(
        SB + OFF_T32, nullptr, SB + WO_D1B, SB + OFF_UP1, L0, CNT, 0, D0);

    // output block
    conv3_bc<4, 0, 2, true><<<nblk_w(VC0 * 2), 256>>>(
        SB + OFF_UP1, nullptr, SB + WO_OA, SB + OFF_SKIP0, L0, CNT, 0, D0);
    conv_out_bc<<<nblk_w(VC0), 256>>>(SB + OFF_SKIP0, SB + WO_OB, out, L0, CNT);
}

// round 7
// speedup vs baseline: 1.8110x; 1.8110x over previous
#include <cuda_runtime.h>

// ---------------------------------------------------------------------------
// Sparse masked 3D U-Net (presetUResNet) on 96^3 grid, fp32.
// R6: R1 conv kernels (channel-major features, input-broadcast + coalesced
// weight loads) + SORTED occupancy lists (chunk count -> scan -> ordered
// scatter) so the 4-8 voxels sharing a warp are spatially adjacent.
// ---------------------------------------------------------------------------

constexpr int D0 = 96, D1 = 48, D2 = 24;
constexpr int V0 = D0 * D0 * D0;   // 884736
constexpr int V1 = D1 * D1 * D1;   // 110592
constexpr int V2 = D2 * D2 * D2;   // 13824

// ---- scratch arena layout (floats), feature buffers channel-major [c][v] ----
constexpr int OFF_XM    = 0;                    // 1  * V0
constexpr int OFF_SKIP0 = OFF_XM    + V0;       // 16 * V0
constexpr int OFF_UP1   = OFF_SKIP0 + 16 * V0;  // 16 * V0
constexpr int OFF_T32   = OFF_UP1   + 16 * V0;  // 32 * V0
constexpr int OFF_HA    = OFF_T32   + 32 * V0;  // 32 * V1
constexpr int OFF_HB    = OFF_HA    + 32 * V1;  // 32 * V1
constexpr int OFF_S1    = OFF_HB    + 32 * V1;  // 32 * V1
constexpr int OFF_H64   = OFF_S1    + 32 * V1;  // 64 * V1
constexpr int OFF_CA    = OFF_H64   + 64 * V1;  // 64 * V2
constexpr int OFF_CB    = OFF_CA    + 64 * V2;  // 64 * V2
constexpr int FEAT_END  = OFF_CB    + 64 * V2;
constexpr int OFF_M1    = FEAT_END;             // V1 mask
constexpr int OFF_M2    = OFF_M1 + V1;          // V2 mask
constexpr int OFF_W     = OFF_M2 + V2;
// transposed weights: layout [(ci*K3 + t)*Copad + o]
constexpr int WO_IN  = OFF_W;
constexpr int WO_E0D = WO_IN  + 1  * 27 * 16;
constexpr int WO_E0A = WO_E0D + 16 * 8  * 32;
constexpr int WO_E0B = WO_E0A + 32 * 27 * 32;
constexpr int WO_E1D = WO_E0B + 32 * 27 * 32;
constexpr int WO_E1A = WO_E1D + 32 * 8  * 64;
constexpr int WO_E1B = WO_E1A + 64 * 27 * 64;
constexpr int WO_D0U = WO_E1B + 64 * 27 * 64;
constexpr int WO_D0A = WO_D0U + 64 * 8  * 32;
constexpr int WO_D0B = WO_D0A + 64 * 27 * 64;
constexpr int WO_D1U = WO_D0B + 64 * 27 * 32;
constexpr int WO_D1A = WO_D1U + 32 * 8  * 16;
constexpr int WO_D1B = WO_D1A + 32 * 27 * 32;
constexpr int WO_OA  = WO_D1B + 32 * 27 * 16;
constexpr int WO_OB  = WO_OA  + 16 * 27 * 16;
constexpr int SCRATCH_TOTAL = WO_OB + 16 * 27 * 8;

// sorted-list build: 1024-voxel chunks
constexpr int CH0 = (V0 + 1023) / 1024;   // 864
constexpr int CH1 = (V1 + 1023) / 1024;   // 108
constexpr int CH2 = (V2 + 1023) / 1024;   // 14
constexpr int CHT = CH0 + CH1 + CH2;      // 986

__device__ __align__(256) float g_scratch[SCRATCH_TOTAL];  // zero-initialized
__device__ int g_list0[V0];
__device__ int g_list1[V1];
__device__ int g_list2[V2];
__device__ int g_cnt[4];
__device__ int g_chunkcnt[CHT];
__device__ int g_chunkoff[CHT];

// ---------------------------------------------------------------------------
// prep kernels
// ---------------------------------------------------------------------------

__global__ void prep1_kernel(const float* __restrict__ x,
                             const float* __restrict__ occ,
                             float* __restrict__ out, int outn) {
    int stride = gridDim.x * blockDim.x;
    int gt = blockIdx.x * blockDim.x + threadIdx.x;
    float4 z4 = make_float4(0.f, 0.f, 0.f, 0.f);
    float4* o4 = reinterpret_cast<float4*>(out);
    for (int i = gt; i < outn / 4; i += stride) o4[i] = z4;
    for (int i = gt; i < V0; i += stride) g_scratch[OFF_XM + i] = x[i] * occ[i];
    for (int i = gt; i < V1; i += stride) {
        int xx = i % D1, yy = (i / D1) % D1, zz = i / (D1 * D1);
        float m = 0.f;
        #pragma unroll
        for (int dz = 0; dz < 2; dz++)
            #pragma unroll
            for (int dy = 0; dy < 2; dy++)
                #pragma unroll
                for (int dx = 0; dx < 2; dx++)
                    m = fmaxf(m, occ[((2 * zz + dz) * D0 + 2 * yy + dy) * D0 + 2 * xx + dx]);
        g_scratch[OFF_M1 + i] = m;
    }
    for (int i = gt; i < V2; i += stride) {
        int xx = i % D2, yy = (i / D2) % D2, zz = i / (D2 * D2);
        float m = 0.f;
        for (int dz = 0; dz < 4; dz++)
            for (int dy = 0; dy < 4; dy++)
                #pragma unroll
                for (int dx = 0; dx < 4; dx++)
                    m = fmaxf(m, occ[((4 * zz + dz) * D0 + 4 * yy + dy) * D0 + 4 * xx + dx]);
        g_scratch[OFF_M2 + i] = m;
    }
    for (int i = gt; i < CHT; i += stride) g_chunkcnt[i] = 0;
}

// count occupied voxels per 1024-chunk. block = 256 thr = 1 chunk; y = level.
__global__ void count_kernel(const float* __restrict__ occ) {
    const float* mask; int n, cbase;
    if (blockIdx.y == 0)      { mask = occ;                n = V0; cbase = 0; }
    else if (blockIdx.y == 1) { mask = g_scratch + OFF_M1; n = V1; cbase = CH0; }
    else                      { mask = g_scratch + OFF_M2; n = V2; cbase = CH0 + CH1; }
    int chunk = blockIdx.x;
    long base = (long)chunk * 1024;
    if (base >= n) return;
    int cnt = 0;
    #pragma unroll
    for (int r = 0; r < 4; r++) {
        long i = base + r * 256 + threadIdx.x;
        if (i < n && mask[i] > 0.5f) cnt++;
    }
    #pragma unroll
    for (int s = 16; s > 0; s >>= 1) cnt += __shfl_down_sync(0xffffffffu, cnt, s);
    if ((threadIdx.x & 31) == 0 && cnt) atomicAdd(&g_chunkcnt[cbase + chunk], cnt);
}

// exclusive scan of chunk counts per level (single block)
__global__ void scan_kernel() {
    __shared__ int s[1024];
    int t = threadIdx.x;
    int segBase[3] = {0, CH0, CH0 + CH1};
    int segCnt[3]  = {CH0, CH1, CH2};
    for (int seg = 0; seg < 3; seg++) {
        int val = (t < segCnt[seg]) ? g_chunkcnt[segBase[seg] + t] : 0;
        s[t] = val;
        __syncthreads();
        for (int d = 1; d < 1024; d <<= 1) {
            int add = (t >= d) ? s[t - d] : 0;
            __syncthreads();
            s[t] += add;
            __syncthreads();
        }
        if (t < segCnt[seg]) g_chunkoff[segBase[seg] + t] = s[t] - val;
        if (t == segCnt[seg] - 1) g_cnt[seg] = s[t];
        __syncthreads();
    }
}

// ordered scatter: one warp per chunk -> globally sorted lists
__global__ void scatter_kernel(const float* __restrict__ occ) {
    const float* mask; int n, cbase; int* list;
    if (blockIdx.y == 0)      { mask = occ;                n = V0; cbase = 0;        list = g_list0; }
    else if (blockIdx.y == 1) { mask = g_scratch + OFF_M1; n = V1; cbase = CH0;      list = g_list1; }
    else                      { mask = g_scratch + OFF_M2; n = V2; cbase = CH0+CH1;  list = g_list2; }
    int chunk = blockIdx.x;
    long cb = (long)chunk * 1024;
    if (cb >= n) return;
    int lane = threadIdx.x & 31;
    int base = g_chunkoff[cbase + chunk];
    for (int r = 0; r < 32; r++) {
        long i = cb + r * 32 + lane;
        bool pred = (i < n) && (mask[i] > 0.5f);
        unsigned bal = __ballot_sync(0xffffffffu, pred);
        if (pred) list[base + __popc(bal & ((1u << lane) - 1))] = (int)i;
        base += __popc(bal);
    }
}

// weights: w[(o*Cin + ci)*K3 + t]  -->  wt[(ci*K3 + t)*Copad + o]  (pad zeros)
struct WPtrs { const float* p[15]; };
__device__ const int TW_DIMS[15][4] = {
    {16, 1, 27, 16}, {32, 16, 8, 32}, {32, 32, 27, 32}, {32, 32, 27, 32},
    {64, 32, 8, 64}, {64, 64, 27, 64}, {64, 64, 27, 64}, {32, 64, 8, 32},
    {64, 64, 27, 64}, {32, 64, 27, 32}, {16, 32, 8, 16}, {32, 32, 27, 32},
    {16, 32, 27, 16}, {16, 16, 27, 16}, {5, 16, 27, 8}};
__device__ const int TW_OFF[15] = {
    WO_IN, WO_E0D, WO_E0A, WO_E0B, WO_E1D, WO_E1A, WO_E1B, WO_D0U,
    WO_D0A, WO_D0B, WO_D1U, WO_D1A, WO_D1B, WO_OA, WO_OB};

__global__ void tw_kernel(WPtrs wp) {
    int e = blockIdx.y;
    int Cout = TW_DIMS[e][0], Cin = TW_DIMS[e][1], K3 = TW_DIMS[e][2], Copad = TW_DIMS[e][3];
    const float* w = wp.p[e];
    float* wt = g_scratch + TW_OFF[e];
    int total = Cin * K3 * Copad;
    for (int i = blockIdx.x * blockDim.x + threadIdx.x; i < total;
         i += gridDim.x * blockDim.x) {
        int o = i % Copad;
        int r = i / Copad;
        int ci = r / K3, t = r % K3;
        wt[i] = (o < Cout) ? w[(o * Cin + ci) * K3 + t] : 0.f;
    }
}

// ---------------------------------------------------------------------------
// gather conv kernels (R1 pattern: lanes = (voxel, cout-group-of-4))
// ---------------------------------------------------------------------------

template <int CINA, int CINB, int COUT, int COPAD, bool RELU>
__global__ __launch_bounds__(256)
void conv3_kernel(const float* __restrict__ inA, const float* __restrict__ inB,
                  const float* __restrict__ wt, float* __restrict__ out,
                  const int* __restrict__ list, const int* __restrict__ cnt,
                  int cntIdx, int D) {
    const int vol = D * D * D;
    const int CG = COPAD / 4;
    int n = cnt[cntIdx];
    int total = n * CG;
    for (int w = blockIdx.x * blockDim.x + threadIdx.x; w < total;
         w += gridDim.x * blockDim.x) {
        int v = list[w / CG];
        int cg = w % CG;
        int x0 = v % D, y0 = (v / D) % D, z0 = v / (D * D);
        float4 acc = make_float4(0.f, 0.f, 0.f, 0.f);
        for (int dz = -1; dz <= 1; dz++) {
            int zz = z0 + dz;
            if ((unsigned)zz >= (unsigned)D) continue;
            for (int dy = -1; dy <= 1; dy++) {
                int yy = y0 + dy;
                if ((unsigned)yy >= (unsigned)D) continue;
                for (int dx = -1; dx <= 1; dx++) {
                    int xx = x0 + dx;
                    if ((unsigned)xx >= (unsigned)D) continue;
                    int t = ((dz + 1) * 3 + (dy + 1)) * 3 + (dx + 1);
                    int noff = (zz * D + yy) * D + xx;
                    const float* ip = inA + noff;
                    const float* wp = wt + t * COPAD + cg * 4;
                    #pragma unroll
                    for (int ci = 0; ci < CINA; ci++) {
                        float iv = __ldg(ip); ip += vol;
                        float4 wv = *reinterpret_cast<const float4*>(wp);
                        wp += 27 * COPAD;
                        acc.x += iv * wv.x; acc.y += iv * wv.y;
                        acc.z += iv * wv.z; acc.w += iv * wv.w;
                    }
                    if (CINB > 0) {
                        const float* ip2 = inB + noff;
                        #pragma unroll
                        for (int ci = 0; ci < CINB; ci++) {
                            float iv = __ldg(ip2); ip2 += vol;
                            float4 wv = *reinterpret_cast<const float4*>(wp);
                            wp += 27 * COPAD;
                            acc.x += iv * wv.x; acc.y += iv * wv.y;
                            acc.z += iv * wv.z; acc.w += iv * wv.w;
                        }
                    }
                }
            }
        }
        if (RELU) {
            acc.x = fmaxf(acc.x, 0.f); acc.y = fmaxf(acc.y, 0.f);
            acc.z = fmaxf(acc.z, 0.f); acc.w = fmaxf(acc.w, 0.f);
        }
        int co = cg * 4;
        out[(co + 0) * vol + v] = acc.x;
        if (co + 1 < COUT) out[(co + 1) * vol + v] = acc.y;
        if (co + 2 < COUT) out[(co + 2) * vol + v] = acc.z;
        if (co + 3 < COUT) out[(co + 3) * vol + v] = acc.w;
    }
}

template <int CIN, int COUT, int COPAD>
__global__ __launch_bounds__(256)
void down2_kernel(const float* __restrict__ in, const float* __restrict__ wt,
                  float* __restrict__ out, const int* __restrict__ list,
                  const int* __restrict__ cnt, int cntIdx, int Dc) {
    const int Df = Dc * 2;
    const int volf = Df * Df * Df;
    const int volc = Dc * Dc * Dc;
    const int CG = COPAD / 4;
    int n = cnt[cntIdx];
    int total = n * CG;
    for (int w = blockIdx.x * blockDim.x + threadIdx.x; w < total;
         w += gridDim.x * blockDim.x) {
        int v = list[w / CG];
        int cg = w % CG;
        int x0 = v % Dc, y0 = (v / Dc) % Dc, z0 = v / (Dc * Dc);
        float4 acc = make_float4(0.f, 0.f, 0.f, 0.f);
        #pragma unroll
        for (int t = 0; t < 8; t++) {
            int tz = t >> 2, ty = (t >> 1) & 1, tx = t & 1;
            int noff = ((2 * z0 + tz) * Df + (2 * y0 + ty)) * Df + (2 * x0 + tx);
            const float* ip = in + noff;
            const float* wp = wt + t * COPAD + cg * 4;
            #pragma unroll
            for (int ci = 0; ci < CIN; ci++) {
                float iv = __ldg(ip); ip += volf;
                float4 wv = *reinterpret_cast<const float4*>(wp);
                wp += 8 * COPAD;
                acc.x += iv * wv.x; acc.y += iv * wv.y;
                acc.z += iv * wv.z; acc.w += iv * wv.w;
            }
        }
        int co = cg * 4;
        out[(co + 0) * volc + v] = acc.x;
        out[(co + 1) * volc + v] = acc.y;
        out[(co + 2) * volc + v] = acc.z;
        out[(co + 3) * volc + v] = acc.w;
    }
}

template <int CIN, int COUT, int COPAD>
__global__ __launch_bounds__(256)
void up2_kernel(const float* __restrict__ in, const float* __restrict__ wt,
                float* __restrict__ out, const int* __restrict__ list,
                const int* __restrict__ cnt, int cntIdx, int Df) {
    const int Dc = Df / 2;
    const int volf = Df * Df * Df;
    const int volc = Dc * Dc * Dc;
    const int CG = COPAD / 4;
    int n = cnt[cntIdx];
    int total = n * CG;
    for (int w = blockIdx.x * blockDim.x + threadIdx.x; w < total;
         w += gridDim.x * blockDim.x) {
        int v = list[w / CG];
        int cg = w % CG;
        int x0 = v % Df, y0 = (v / Df) % Df, z0 = v / (Df * Df);
        int t = ((1 - (z0 & 1)) * 2 + (1 - (y0 & 1))) * 2 + (1 - (x0 & 1));
        int coff = ((z0 >> 1) * Dc + (y0 >> 1)) * Dc + (x0 >> 1);
        float4 acc = make_float4(0.f, 0.f, 0.f, 0.f);
        const float* ip = in + coff;
        const float* wp = wt + t * COPAD + cg * 4;
        #pragma unroll
        for (int ci = 0; ci < CIN; ci++) {
            float iv = __ldg(ip); ip += volc;
            float4 wv = *reinterpret_cast<const float4*>(wp);
            wp += 8 * COPAD;
            acc.x += iv * wv.x; acc.y += iv * wv.y;
            acc.z += iv * wv.z; acc.w += iv * wv.w;
        }
        int co = cg * 4;
        out[(co + 0) * volf + v] = acc.x;
        out[(co + 1) * volf + v] = acc.y;
        out[(co + 2) * volf + v] = acc.z;
        out[(co + 3) * volf + v] = acc.w;
    }
}

// ---------------------------------------------------------------------------
// launch
// ---------------------------------------------------------------------------

extern "C" void kernel_launch(void* const* d_in, const int* in_sizes, int n_in,
                              void* d_out, int out_size) {
    (void)in_sizes; (void)n_in;
    const float* x   = (const float*)d_in[0];
    const float* occ = (const float*)d_in[1];
    float* out = (float*)d_out;

    float* SB = nullptr;
    int *L0 = nullptr, *L1 = nullptr, *L2 = nullptr, *CNT = nullptr;
    cudaGetSymbolAddress((void**)&SB,  g_scratch);
    cudaGetSymbolAddress((void**)&L0,  g_list0);
    cudaGetSymbolAddress((void**)&L1,  g_list1);
    cudaGetSymbolAddress((void**)&L2,  g_list2);
    cudaGetSymbolAddress((void**)&CNT, g_cnt);

    const int NT = 256;
    const int NB = 2048;

    // prep: zero d_out, masked input, coarse masks, reset chunk counters
    prep1_kernel<<<1024, NT>>>(x, occ, out, out_size);
    // sorted list build: count -> scan -> ordered scatter
    count_kernel<<<dim3(CH0, 3), NT>>>(occ);
    scan_kernel<<<1, 1024>>>();
    scatter_kernel<<<dim3(CH0, 3), 32>>>(occ);
    // weight transposes
    WPtrs wp;
    for (int i = 0; i < 15; i++) wp.p[i] = (const float*)d_in[2 + i];
    tw_kernel<<<dim3(216, 15), NT>>>(wp);

    // U-Net pipeline (channel-major features)
    conv3_kernel<1, 0, 16, 16, false><<<NB, NT>>>(
        SB + OFF_XM, nullptr, SB + WO_IN, SB + OFF_SKIP0, L0, CNT, 0, D0);

    // encoder level 0
    down2_kernel<16, 32, 32><<<NB, NT>>>(
        SB + OFF_SKIP0, SB + WO_E0D, SB + OFF_HA, L1, CNT, 1, D1);
    conv3_kernel<32, 0, 32, 32, true><<<NB, NT>>>(
        SB + OFF_HA, nullptr, SB + WO_E0A, SB + OFF_HB, L1, CNT, 1, D1);
    conv3_kernel<32, 0, 32, 32, false><<<NB, NT>>>(
        SB + OFF_HB, nullptr, SB + WO_E0B, SB + OFF_S1, L1, CNT, 1, D1);

    // encoder level 1
    down2_kernel<32, 64, 64><<<NB, NT>>>(
        SB + OFF_S1, SB + WO_E1D, SB + OFF_CA, L2, CNT, 2, D2);
    conv3_kernel<64, 0, 64, 64, true><<<NB, NT>>>(
        SB + OFF_CA, nullptr, SB + WO_E1A, SB + OFF_CB, L2, CNT, 2, D2);
    conv3_kernel<64, 0, 64, 64, false><<<NB, NT>>>(
        SB + OFF_CB, nullptr, SB + WO_E1B, SB + OFF_CA, L2, CNT, 2, D2);

    // decoder stage 0 (to level 1)
    up2_kernel<64, 32, 32><<<NB, NT>>>(
        SB + OFF_CA, SB + WO_D0U, SB + OFF_HA, L1, CNT, 1, D1);
    conv3_kernel<32, 32, 64, 64, true><<<NB, NT>>>(
        SB + OFF_HA, SB + OFF_S1, SB + WO_D0A, SB + OFF_H64, L1, CNT, 1, D1);
    conv3_kernel<64, 0, 32, 32, false><<<NB, NT>>>(
        SB + OFF_H64, nullptr, SB + WO_D0B, SB + OFF_HB, L1, CNT, 1, D1);

    // decoder stage 1 (to level 0)
    up2_kernel<32, 16, 16><<<NB, NT>>>(
        SB + OFF_HB, SB + WO_D1U, SB + OFF_UP1, L0, CNT, 0, D0);
    conv3_kernel<16, 16, 32, 32, true><<<NB, NT>>>(
        SB + OFF_UP1, SB + OFF_SKIP0, SB + WO_D1A, SB + OFF_T32, L0, CNT, 0, D0);
    conv3_kernel<32, 0, 16, 16, false><<<NB, NT>>>(
        SB + OFF_T32, nullptr, SB + WO_D1B, SB + OFF_UP1, L0, CNT, 0, D0);

    // output block
    conv3_kernel<16, 0, 16, 16, true><<<NB, NT>>>(
        SB + OFF_UP1, nullptr, SB + WO_OA, SB + OFF_SKIP0, L0, CNT, 0, D0);
    conv3_kernel<16, 0, 5, 8, false><<<NB, NT>>>(
        SB + OFF_SKIP0, nullptr, SB + WO_OB, out, L0, CNT, 0, D0);
}